// round 14
// baseline (speedup 1.0000x reference)
#include <cuda_runtime.h>
#include <cuda_bf16.h>
#include <math.h>
#include <cstdint>

#define H 128
#define BG 1024
#define NPER 32
#define NTOT (BG * NPER)      // 32768 nodes
#define ETOT (2 * NTOT)       // 65536 edges
#define NNODE 100000

#define SROW 136              // scores kernel smem row (bf16)
#define TSZE (128 * SROW)
#define T_NT 8                // n-tiles per block in scores kernel

#define SROW2 72              // mid-GEMM smem row (bf16), BK=64 + 8 pad
#define ATILE2 (64 * SROW2)   // 4608 elems
#define BTILE2 (128 * SROW2)  // 9216 elems
#define STG2 (2 * ATILE2 + 2 * BTILE2)   // 27648 elems per stage (55296 B)

// ---------------- device scratch ----------------
__device__ float g_h[NTOT * H];
__device__ __nv_bfloat16 g_h_hi[NTOT * H];
__device__ __nv_bfloat16 g_h_lo[NTOT * H];
__device__ float g_pre[NTOT * 640];       // [hin(128) | hout(128) | gg(384)] per node
__device__ __nv_bfloat16 g_m_hi[NTOT * 2 * H];
__device__ __nv_bfloat16 g_m_lo[NTOT * 2 * H];
__device__ float g_a[NTOT * 3 * H];
__device__ float g_hn[NTOT * H];
__device__ __nv_bfloat16 g_hn_hi[NTOT * H];
__device__ __nv_bfloat16 g_hn_lo[NTOT * H];
__device__ float g_t2[NTOT * H];
__device__ float g_vn[BG * H];
__device__ __nv_bfloat16 g_vn_hi[BG * H];
__device__ __nv_bfloat16 g_vn_lo[BG * H];
__device__ float g_u[BG * H];
__device__ __nv_bfloat16 g_cat_hi[BG * 2 * H];
__device__ __nv_bfloat16 g_cat_lo[BG * 2 * H];
__device__ float g_sh[BG * H];
__device__ __nv_bfloat16 g_sh_hi[BG * H];
__device__ __nv_bfloat16 g_sh_lo[BG * H];
__device__ __nv_bfloat16 g_wcat_hi[640 * H];   // [wT0;wT1;whh] as [out][in]
__device__ __nv_bfloat16 g_wcat_lo[640 * H];
__device__ float g_bcat[640];                  // [ggnn_b(256); gru_bhh(384)]
__device__ __nv_bfloat16 g_wih_hi[3 * H * 2 * H];
__device__ __nv_bfloat16 g_wih_lo[3 * H * 2 * H];
__device__ __nv_bfloat16 g_W1_hi[H * H];
__device__ __nv_bfloat16 g_W1_lo[H * H];
__device__ __nv_bfloat16 g_W2_hi[H * H];
__device__ __nv_bfloat16 g_W2_lo[H * H];
__device__ __nv_bfloat16 g_W3_hi[H * 2 * H];
__device__ __nv_bfloat16 g_W3_lo[H * 2 * H];
__device__ __nv_bfloat16 g_emb_hi[NNODE * H];
__device__ __nv_bfloat16 g_emb_lo[NNODE * H];

// ======================= helpers =======================
__device__ __forceinline__ uint32_t smem_u32(const void* p) {
    uint32_t a;
    asm("{ .reg .u64 t; cvta.to.shared.u64 t, %1; cvt.u32.u64 %0, t; }" : "=r"(a) : "l"(p));
    return a;
}
__device__ __forceinline__ void ldsm_x4(uint32_t* r, uint32_t addr) {
    asm volatile("ldmatrix.sync.aligned.m8n8.x4.shared.b16 {%0,%1,%2,%3}, [%4];"
        : "=r"(r[0]), "=r"(r[1]), "=r"(r[2]), "=r"(r[3]) : "r"(addr));
}
__device__ __forceinline__ void mma_bf16(float* c, const uint32_t* a, const uint32_t* b) {
    asm volatile(
        "mma.sync.aligned.m16n8k16.row.col.f32.bf16.bf16.f32 "
        "{%0,%1,%2,%3}, {%4,%5,%6,%7}, {%8,%9}, {%0,%1,%2,%3};"
        : "+f"(c[0]), "+f"(c[1]), "+f"(c[2]), "+f"(c[3])
        : "r"(a[0]), "r"(a[1]), "r"(a[2]), "r"(a[3]),
          "r"(b[0]), "r"(b[1]));
}
__device__ __forceinline__ void cp16(uint32_t dst, const void* src, bool p) {
    int sz = p ? 16 : 0;
    asm volatile("cp.async.cg.shared.global [%0], [%1], 16, %2;"
        :: "r"(dst), "l"(src), "r"(sz) : "memory");
}
__device__ __forceinline__ void split2(float x, __nv_bfloat16* hi, __nv_bfloat16* lo) {
    __nv_bfloat16 h = __float2bfloat16_rn(x);
    *hi = h;
    *lo = __float2bfloat16_rn(x - __bfloat162float(h));
}
__device__ __forceinline__ uint32_t pack2(float a, float b, float* rlo0, float* rlo1) {
    __nv_bfloat16 ha = __float2bfloat16_rn(a), hb = __float2bfloat16_rn(b);
    *rlo0 = a - __bfloat162float(ha);
    *rlo1 = b - __bfloat162float(hb);
    __nv_bfloat162 p = __halves2bfloat162(ha, hb);
    return *(uint32_t*)&p;
}
__device__ __forceinline__ uint32_t packlo(float l0, float l1) {
    __nv_bfloat162 p = __halves2bfloat162(__float2bfloat16_rn(l0), __float2bfloat16_rn(l1));
    return *(uint32_t*)&p;
}

// ============ mid split-bf16 HMMA GEMM: C[M,Nc] = A[M,K] @ B[Nc,K]^T + bias ============
// block tile 64x128, BK=64 DOUBLE-BUFFERED, 8 warps (2m x 4n), warp 32x32. 2 CTAs/SM.
__global__ __launch_bounds__(256, 2) void hmma_gemm64(
    const __nv_bfloat16* __restrict__ Ahi, const __nv_bfloat16* __restrict__ Alo,
    const __nv_bfloat16* __restrict__ Bhi, const __nv_bfloat16* __restrict__ Blo,
    const float* __restrict__ bias, float* __restrict__ C,
    __nv_bfloat16* __restrict__ Chi, __nv_bfloat16* __restrict__ Clo,
    int M, int Nc, int K)
{
    extern __shared__ __align__(16) __nv_bfloat16 smem[];
    const int tid = threadIdx.x;
    const int m0 = blockIdx.y * 64;
    const int n0 = blockIdx.x * 128;
    const int w = tid >> 5, lane = tid & 31;
    const int wm = (w >> 2) * 32, wn = (w & 3) * 32;
    const int Kv = K >> 3;
    const int nk = K >> 6;        // number of 64-wide K chunks

    float acc[2][4][4];
#pragma unroll
    for (int i = 0; i < 2; i++)
#pragma unroll
        for (int j = 0; j < 4; j++)
#pragma unroll
            for (int v = 0; v < 4; v++) acc[i][j][v] = 0.f;

    const uint32_t sbase = smem_u32(smem);
    const int aRow = (lane & 7) + ((lane >> 3) & 1) * 8;
    const int aK   = (lane >> 4) * 8;
    const int bRow = (lane & 7) + (lane >> 4) * 8;
    const int bK   = ((lane >> 3) & 1) * 8;

    auto fill = [&](int c, int s) {
        const uint32_t st = sbase + s * STG2 * 2;
        const uint32_t aHi = st, aLo = st + ATILE2 * 2;
        const uint32_t bHi = st + 2 * ATILE2 * 2, bLo = bHi + BTILE2 * 2;
        const int kv0 = c * 8;
#pragma unroll
        for (int it = 0; it < 2; it++) {
            int idx = tid + it * 256;
            int row = idx >> 3, u = idx & 7;
            cp16(aHi + (row * SROW2 + u * 8) * 2, (const uint4*)Ahi + (size_t)(m0 + row) * Kv + kv0 + u, true);
            cp16(aLo + (row * SROW2 + u * 8) * 2, (const uint4*)Alo + (size_t)(m0 + row) * Kv + kv0 + u, true);
        }
#pragma unroll
        for (int it = 0; it < 4; it++) {
            int idx = tid + it * 256;
            int row = idx >> 3, u = idx & 7;
            int gr = n0 + row;
            bool p = gr < Nc;
            size_t off = p ? ((size_t)gr * Kv + kv0 + u) : 0;
            cp16(bHi + (row * SROW2 + u * 8) * 2, (const uint4*)Bhi + off, p);
            cp16(bLo + (row * SROW2 + u * 8) * 2, (const uint4*)Blo + off, p);
        }
        asm volatile("cp.async.commit_group;" ::: "memory");
    };

    fill(0, 0);
    if (nk > 1) fill(1, 1);

    for (int c = 0; c < nk; c++) {
        if (c + 1 < nk) asm volatile("cp.async.wait_group 1;" ::: "memory");
        else            asm volatile("cp.async.wait_group 0;" ::: "memory");
        __syncthreads();
        const int s = c & 1;
        const uint32_t st = sbase + s * STG2 * 2;
        const uint32_t aHiB = st, aLoB = st + ATILE2 * 2;
        const uint32_t bHiB = st + 2 * ATILE2 * 2, bLoB = bHiB + BTILE2 * 2;

#pragma unroll
        for (int ks = 0; ks < 4; ks++) {
            const int k0 = ks * 16;
            uint32_t ahi[2][4], alo[2][4], bhi[2][4], blo[2][4];
#pragma unroll
            for (int i = 0; i < 2; i++) {
                uint32_t off = (uint32_t)((wm + i * 16 + aRow) * SROW2 + k0 + aK) * 2;
                ldsm_x4(ahi[i], aHiB + off);
                ldsm_x4(alo[i], aLoB + off);
            }
#pragma unroll
            for (int q = 0; q < 2; q++) {
                uint32_t off = (uint32_t)((wn + q * 16 + bRow) * SROW2 + k0 + bK) * 2;
                ldsm_x4(bhi[q], bHiB + off);
                ldsm_x4(blo[q], bLoB + off);
            }
#pragma unroll
            for (int i = 0; i < 2; i++)
#pragma unroll
                for (int j = 0; j < 4; j++) {
                    const uint32_t* bh2 = &bhi[j >> 1][(j & 1) * 2];
                    const uint32_t* bl2 = &blo[j >> 1][(j & 1) * 2];
                    mma_bf16(acc[i][j], ahi[i], bh2);
                    mma_bf16(acc[i][j], alo[i], bh2);
                    mma_bf16(acc[i][j], ahi[i], bl2);
                }
        }
        __syncthreads();
        if (c + 2 < nk) fill(c + 2, s);
    }

#pragma unroll
    for (int i = 0; i < 2; i++) {
        int row = m0 + wm + i * 16 + (lane >> 2);
#pragma unroll
        for (int j = 0; j < 4; j++) {
            int col = n0 + wn + j * 8 + (lane & 3) * 2;
            if (col < Nc) {
                float b0 = bias ? bias[col] : 0.f;
                float b1 = bias ? bias[col + 1] : 0.f;
                float v0 = acc[i][j][0] + b0, v1 = acc[i][j][1] + b1;
                float v2 = acc[i][j][2] + b0, v3 = acc[i][j][3] + b1;
                *(float2*)&C[(size_t)row * Nc + col] = make_float2(v0, v1);
                *(float2*)&C[(size_t)(row + 8) * Nc + col] = make_float2(v2, v3);
                if (Chi) {
                    float l0, l1;
                    uint32_t ph = pack2(v0, v1, &l0, &l1);
                    *(uint32_t*)&Chi[(size_t)row * Nc + col] = ph;
                    *(uint32_t*)&Clo[(size_t)row * Nc + col] = packlo(l0, l1);
                    uint32_t ph2 = pack2(v2, v3, &l0, &l1);
                    *(uint32_t*)&Chi[(size_t)(row + 8) * Nc + col] = ph2;
                    *(uint32_t*)&Clo[(size_t)(row + 8) * Nc + col] = packlo(l0, l1);
                }
            }
        }
    }
}

// ============ scores GEMM: C[1024,100000] = sh @ emb^T — 512 threads, 16 warps ============
// block tile 128x128 per n-step, warp grid 4m x 4n, warp tile 32x32. T_NT n-steps/block.
__global__ __launch_bounds__(512) void scores_pipe(float* __restrict__ C) {
    extern __shared__ __align__(16) __nv_bfloat16 smem[];
    __nv_bfloat16* sAhi = smem;
    __nv_bfloat16* sAlo = smem + TSZE;
    __nv_bfloat16* sB   = smem + 2 * TSZE;   // stage s: hi at (2s)*TSZE, lo at (2s+1)*TSZE
    const int tid = threadIdx.x;
    const int m0 = blockIdx.y * 128;
    const int nb0 = blockIdx.x * (T_NT * 128);

    const uint4* bh = (const uint4*)g_emb_hi;
    const uint4* bl = (const uint4*)g_emb_lo;

    // group 0: B tile 0 + A tiles
    {
#pragma unroll
        for (int it = 0; it < 4; it++) {
            int idx = tid + it * 512;
            int row = idx >> 4, u = idx & 15;
            int gr = nb0 + row;
            bool p = gr < NNODE;
            size_t off = p ? ((size_t)gr * 16 + u) : 0;
            cp16(smem_u32(sB + row * SROW + u * 8), bh + off, p);
            cp16(smem_u32(sB + TSZE + row * SROW + u * 8), bl + off, p);
        }
        const uint4* ah = (const uint4*)g_sh_hi;
        const uint4* al = (const uint4*)g_sh_lo;
#pragma unroll
        for (int it = 0; it < 4; it++) {
            int idx = tid + it * 512;
            int row = idx >> 4, u = idx & 15;
            cp16(smem_u32(sAhi + row * SROW + u * 8), ah + (size_t)(m0 + row) * 16 + u, true);
            cp16(smem_u32(sAlo + row * SROW + u * 8), al + (size_t)(m0 + row) * 16 + u, true);
        }
        asm volatile("cp.async.commit_group;" ::: "memory");
    }
    // group 1: B tile 1
    {
#pragma unroll
        for (int it = 0; it < 4; it++) {
            int idx = tid + it * 512;
            int row = idx >> 4, u = idx & 15;
            int gr = nb0 + 128 + row;
            bool p = gr < NNODE;
            size_t off = p ? ((size_t)gr * 16 + u) : 0;
            cp16(smem_u32(sB + 2 * TSZE + row * SROW + u * 8), bh + off, p);
            cp16(smem_u32(sB + 3 * TSZE + row * SROW + u * 8), bl + off, p);
        }
        asm volatile("cp.async.commit_group;" ::: "memory");
    }

    const uint32_t aHiB = smem_u32(sAhi), aLoB = smem_u32(sAlo);
    const int w = tid >> 5, lane = tid & 31;
    const int wm = (w >> 2) * 32, wn = (w & 3) * 32;
    const int aRow = (lane & 7) + ((lane >> 3) & 1) * 8;
    const int aK   = (lane >> 4) * 8;
    const int bRow = (lane & 7) + (lane >> 4) * 8;
    const int bK   = ((lane >> 3) & 1) * 8;

#pragma unroll
    for (int t = 0; t < T_NT; t++) {
        if (t + 1 < T_NT) asm volatile("cp.async.wait_group 1;" ::: "memory");
        else              asm volatile("cp.async.wait_group 0;" ::: "memory");
        __syncthreads();
        const int s = t & 1;
        const uint32_t bHiB = smem_u32(sB + (2 * s) * TSZE);
        const uint32_t bLoB = smem_u32(sB + (2 * s + 1) * TSZE);

        float acc[2][4][4];
#pragma unroll
        for (int i = 0; i < 2; i++)
#pragma unroll
            for (int j = 0; j < 4; j++)
#pragma unroll
                for (int v = 0; v < 4; v++) acc[i][j][v] = 0.f;

#pragma unroll
        for (int ks = 0; ks < 8; ks++) {
            const int k0 = ks * 16;
            uint32_t ahi[2][4], alo[2][4], bhi[2][4], blo[2][4];
#pragma unroll
            for (int i = 0; i < 2; i++) {
                uint32_t off = (uint32_t)((wm + i * 16 + aRow) * SROW + k0 + aK) * 2;
                ldsm_x4(ahi[i], aHiB + off);
                ldsm_x4(alo[i], aLoB + off);
            }
#pragma unroll
            for (int q = 0; q < 2; q++) {
                uint32_t off = (uint32_t)((wn + q * 16 + bRow) * SROW + k0 + bK) * 2;
                ldsm_x4(bhi[q], bHiB + off);
                ldsm_x4(blo[q], bLoB + off);
            }
#pragma unroll
            for (int i = 0; i < 2; i++)
#pragma unroll
                for (int j = 0; j < 4; j++) {
                    const uint32_t* bh2 = &bhi[j >> 1][(j & 1) * 2];
                    const uint32_t* bl2 = &blo[j >> 1][(j & 1) * 2];
                    mma_bf16(acc[i][j], ahi[i], bh2);
                    mma_bf16(acc[i][j], alo[i], bh2);
                    mma_bf16(acc[i][j], ahi[i], bl2);
                }
        }
        __syncthreads();   // all warps done reading stage s

        // prefetch t+2 into stage s before epilogue stores
        if (t + 2 < T_NT) {
            int base = nb0 + (t + 2) * 128;
#pragma unroll
            for (int it = 0; it < 4; it++) {
                int idx = tid + it * 512;
                int row = idx >> 4, u = idx & 15;
                int gr = base + row;
                bool p = gr < NNODE;
                size_t off = p ? ((size_t)gr * 16 + u) : 0;
                cp16(smem_u32(sB + (2 * s) * TSZE + row * SROW + u * 8), bh + off, p);
                cp16(smem_u32(sB + (2 * s + 1) * TSZE + row * SROW + u * 8), bl + off, p);
            }
            asm volatile("cp.async.commit_group;" ::: "memory");
        }

        const int n0 = nb0 + t * 128;
#pragma unroll
        for (int i = 0; i < 2; i++) {
            int row = m0 + wm + i * 16 + (lane >> 2);
#pragma unroll
            for (int j = 0; j < 4; j++) {
                int col = n0 + wn + j * 8 + (lane & 3) * 2;
                if (col < NNODE) {
                    *(float2*)&C[(size_t)row * NNODE + col] =
                        make_float2(acc[i][j][0], acc[i][j][1]);
                    *(float2*)&C[(size_t)(row + 8) * NNODE + col] =
                        make_float2(acc[i][j][2], acc[i][j][3]);
                }
            }
        }
    }
}

// ---------------- conversion / stage kernels ----------------
__global__ void convert_params(const float* __restrict__ gw, const float* __restrict__ ggb,
                               const float* __restrict__ bhh,
                               const float* __restrict__ wih, const float* __restrict__ whh,
                               const float* __restrict__ W1, const float* __restrict__ W2,
                               const float* __restrict__ W3) {
    int i = blockIdx.x * blockDim.x + threadIdx.x;
    if (i < 32768) {                 // ggnn_w [l][in][out] -> wcat rows l*128+out
        int l = i >> 14, r = (i >> 7) & 127, c = i & 127;
        int o = (l * H + c) * H + r;
        split2(gw[i], &g_wcat_hi[o], &g_wcat_lo[o]);
        return;
    }
    i -= 32768;
    if (i < 49152) {                 // whh rows -> wcat rows 256..639
        split2(whh[i], &g_wcat_hi[32768 + i], &g_wcat_lo[32768 + i]);
        return;
    }
    i -= 49152;
    if (i < 98304) { split2(wih[i], &g_wih_hi[i], &g_wih_lo[i]); return; }
    i -= 98304;
    if (i < 16384) { split2(W1[i], &g_W1_hi[i], &g_W1_lo[i]); return; }
    i -= 16384;
    if (i < 16384) { split2(W2[i], &g_W2_hi[i], &g_W2_lo[i]); return; }
    i -= 16384;
    if (i < 32768) { split2(W3[i], &g_W3_hi[i], &g_W3_lo[i]); return; }
    i -= 32768;
    if (i < 640) { g_bcat[i] = (i < 256) ? ggb[i] : bhh[i - 256]; return; }
}

__global__ void convert_emb(const float* __restrict__ e) {
    long i = (long)blockIdx.x * blockDim.x + threadIdx.x;
    if (i >= (long)NNODE * H / 4) return;
    float4 v = ((const float4*)e)[i];
    float l0, l1, l2, l3;
    uint32_t h01 = pack2(v.x, v.y, &l0, &l1);
    uint32_t h23 = pack2(v.z, v.w, &l2, &l3);
    ((uint2*)g_emb_hi)[i] = make_uint2(h01, h23);
    ((uint2*)g_emb_lo)[i] = make_uint2(packlo(l0, l1), packlo(l2, l3));
}

__global__ void embed_gather(const int* __restrict__ x, const float* __restrict__ emb) {
    int idx = blockIdx.x * blockDim.x + threadIdx.x;
    if (idx >= NTOT * H / 4) return;
    int node = idx >> 5;
    int c4 = idx & 31;
    int item = x[node] - 1;
    float4 v = ((const float4*)emb)[(size_t)item * 32 + c4];
    ((float4*)g_h)[idx] = v;
    float l0, l1, l2, l3;
    uint32_t h01 = pack2(v.x, v.y, &l0, &l1);
    uint32_t h23 = pack2(v.z, v.w, &l2, &l3);
    ((uint2*)g_h_hi)[idx] = make_uint2(h01, h23);
    ((uint2*)g_h_lo)[idx] = make_uint2(packlo(l0, l1), packlo(l2, l3));
}

__global__ __launch_bounds__(128) void msg_pass(
    const int* __restrict__ ei, const float* __restrict__ ec,
    const float* __restrict__ idi, const float* __restrict__ odi)
{
    __shared__ float hs[NPER][H];
    __shared__ float ms[NPER][H];
    __shared__ int es[64], ed[64];
    __shared__ float ws[64];
    const int g = blockIdx.x;
    const int f = threadIdx.x;
    const int nb = g * NPER, eb = g * 64;

    if (f < 64) {
        es[f] = ei[eb + f] - nb;
        ed[f] = ei[ETOT + eb + f] - nb;
        ws[f] = ec[eb + f] * idi[eb + f];
    }
    for (int i = 0; i < NPER; i++) {
        hs[i][f] = g_pre[(size_t)(nb + i) * 640 + f];          // hin
        ms[i][f] = 0.f;
    }
    __syncthreads();
    for (int e = 0; e < 64; e++)
        ms[ed[e]][f] += ws[e] * hs[es[e]][f];
    __syncthreads();
    for (int i = 0; i < NPER; i++) {
        size_t o = (size_t)(nb + i) * 2 * H + f;
        split2(ms[i][f], &g_m_hi[o], &g_m_lo[o]);
    }
    __syncthreads();

    if (f < 64) ws[f] = ec[eb + f] * odi[eb + f];
    for (int i = 0; i < NPER; i++) {
        hs[i][f] = g_pre[(size_t)(nb + i) * 640 + H + f];      // hout
        ms[i][f] = 0.f;
    }
    __syncthreads();
    for (int e = 0; e < 64; e++)
        ms[es[e]][f] += ws[e] * hs[ed[e]][f];
    __syncthreads();
    for (int i = 0; i < NPER; i++) {
        size_t o = (size_t)(nb + i) * 2 * H + H + f;
        split2(ms[i][f], &g_m_hi[o], &g_m_lo[o]);
    }
}

__global__ void gru_gates() {
    int idx = blockIdx.x * blockDim.x + threadIdx.x;   // pair index
    if (idx >= NTOT * 64) return;
    int i = idx >> 6, j = (idx & 63) * 2;
    size_t b3 = (size_t)i * 384;
    size_t bg = (size_t)i * 640 + 256;
    float2 a0 = *(float2*)&g_a[b3 + j];
    float2 g0 = *(float2*)&g_pre[bg + j];
    float2 a1 = *(float2*)&g_a[b3 + 128 + j];
    float2 g1 = *(float2*)&g_pre[bg + 128 + j];
    float2 a2 = *(float2*)&g_a[b3 + 256 + j];
    float2 g2 = *(float2*)&g_pre[bg + 256 + j];
    float2 h  = *(float2*)&g_h[(size_t)i * H + j];

    float r0 = 1.f / (1.f + __expf(-(a0.x + g0.x)));
    float r1 = 1.f / (1.f + __expf(-(a0.y + g0.y)));
    float z0 = 1.f / (1.f + __expf(-(a1.x + g1.x)));
    float z1 = 1.f / (1.f + __expf(-(a1.y + g1.y)));
    float n0 = tanhf(a2.x + r0 * g2.x);
    float n1 = tanhf(a2.y + r1 * g2.y);
    float o0 = (1.f - z0) * n0 + z0 * h.x;
    float o1 = (1.f - z1) * n1 + z1 * h.y;

    size_t o = (size_t)i * H + j;
    *(float2*)&g_hn[o] = make_float2(o0, o1);
    float l0, l1;
    uint32_t ph = pack2(o0, o1, &l0, &l1);
    *(uint32_t*)&g_hn_hi[o] = ph;
    *(uint32_t*)&g_hn_lo[o] = packlo(l0, l1);
    if ((i & 31) == 31) {
        size_t ov = (size_t)(i >> 5) * H + j;
        *(float2*)&g_vn[ov] = make_float2(o0, o1);
        *(uint32_t*)&g_vn_hi[ov] = ph;
        *(uint32_t*)&g_vn_lo[ov] = packlo(l0, l1);
    }
}

__global__ __launch_bounds__(128) void attention(
    const float* __restrict__ qw, const float* __restrict__ qb,
    const float* __restrict__ ncnt)
{
    __shared__ float coef[NPER];
    const int g = blockIdx.x;
    const int tid = threadIdx.x;
    const int w = tid >> 5, l = tid & 31;

    for (int ii = 0; ii < 8; ii++) {
        int i = w * 8 + ii;
        int node = g * NPER + i;
        float p = 0.f;
#pragma unroll
        for (int c = 0; c < 4; c++) {
            int fd = l + c * 32;
            float s = g_u[g * H + fd] + g_t2[(size_t)node * H + fd];
            p += qw[fd] / (1.f + __expf(-s));
        }
#pragma unroll
        for (int off = 16; off; off >>= 1)
            p += __shfl_xor_sync(0xffffffff, p, off);
        if (l == 0) coef[i] = (p + qb[0]) * ncnt[node];
    }
    __syncthreads();

    const int f = tid;
    float acc = 0.f;
    for (int i = 0; i < NPER; i++)
        acc += coef[i] * g_hn[(size_t)(g * NPER + i) * H + f];
    size_t o = (size_t)g * 2 * H;
    split2(acc, &g_cat_hi[o + H + f], &g_cat_lo[o + H + f]);
    split2(g_vn[g * H + f], &g_cat_hi[o + f], &g_cat_lo[o + f]);
}

// ---------------- launch ----------------
extern "C" void kernel_launch(void* const* d_in, const int* in_sizes, int n_in,
                              void* d_out, int out_size)
{
    const int*   x       = (const int*)d_in[0];
    const int*   ei      = (const int*)d_in[1];
    const float* ec      = (const float*)d_in[3];
    const float* idi     = (const float*)d_in[4];
    const float* odi     = (const float*)d_in[5];
    const float* ncnt    = (const float*)d_in[6];
    const float* emb     = (const float*)d_in[8];
    const float* ggnn_w  = (const float*)d_in[9];
    const float* ggnn_b  = (const float*)d_in[10];
    const float* gru_wih = (const float*)d_in[11];
    const float* gru_whh = (const float*)d_in[12];
    const float* gru_bih = (const float*)d_in[13];
    const float* gru_bhh = (const float*)d_in[14];
    const float* W1_w = (const float*)d_in[15];
    const float* W1_b = (const float*)d_in[16];
    const float* W2_w = (const float*)d_in[17];
    const float* W2_b = (const float*)d_in[18];
    const float* q_w  = (const float*)d_in[19];
    const float* q_b  = (const float*)d_in[20];
    const float* W3_w = (const float*)d_in[21];
    const float* W3_b = (const float*)d_in[22];
    float* out = (float*)d_out;

    float *p_pre, *p_a, *p_t2, *p_u, *p_sh, *p_bcat;
    __nv_bfloat16 *p_h_hi, *p_h_lo, *p_m_hi, *p_m_lo, *p_hn_hi, *p_hn_lo;
    __nv_bfloat16 *p_vn_hi, *p_vn_lo, *p_cat_hi, *p_cat_lo, *p_sh_hi, *p_sh_lo;
    __nv_bfloat16 *p_wcat_hi, *p_wcat_lo, *p_wih_hi, *p_wih_lo;
    __nv_bfloat16 *p_W1_hi, *p_W1_lo, *p_W2_hi, *p_W2_lo, *p_W3_hi, *p_W3_lo;
    cudaGetSymbolAddress((void**)&p_pre, g_pre);
    cudaGetSymbolAddress((void**)&p_a, g_a);
    cudaGetSymbolAddress((void**)&p_t2, g_t2);
    cudaGetSymbolAddress((void**)&p_u, g_u);
    cudaGetSymbolAddress((void**)&p_sh, g_sh);
    cudaGetSymbolAddress((void**)&p_bcat, g_bcat);
    cudaGetSymbolAddress((void**)&p_h_hi, g_h_hi);
    cudaGetSymbolAddress((void**)&p_h_lo, g_h_lo);
    cudaGetSymbolAddress((void**)&p_m_hi, g_m_hi);
    cudaGetSymbolAddress((void**)&p_m_lo, g_m_lo);
    cudaGetSymbolAddress((void**)&p_hn_hi, g_hn_hi);
    cudaGetSymbolAddress((void**)&p_hn_lo, g_hn_lo);
    cudaGetSymbolAddress((void**)&p_vn_hi, g_vn_hi);
    cudaGetSymbolAddress((void**)&p_vn_lo, g_vn_lo);
    cudaGetSymbolAddress((void**)&p_cat_hi, g_cat_hi);
    cudaGetSymbolAddress((void**)&p_cat_lo, g_cat_lo);
    cudaGetSymbolAddress((void**)&p_sh_hi, g_sh_hi);
    cudaGetSymbolAddress((void**)&p_sh_lo, g_sh_lo);
    cudaGetSymbolAddress((void**)&p_wcat_hi, g_wcat_hi);
    cudaGetSymbolAddress((void**)&p_wcat_lo, g_wcat_lo);
    cudaGetSymbolAddress((void**)&p_wih_hi, g_wih_hi);
    cudaGetSymbolAddress((void**)&p_wih_lo, g_wih_lo);
    cudaGetSymbolAddress((void**)&p_W1_hi, g_W1_hi);
    cudaGetSymbolAddress((void**)&p_W1_lo, g_W1_lo);
    cudaGetSymbolAddress((void**)&p_W2_hi, g_W2_hi);
    cudaGetSymbolAddress((void**)&p_W2_lo, g_W2_lo);
    cudaGetSymbolAddress((void**)&p_W3_hi, g_W3_hi);
    cudaGetSymbolAddress((void**)&p_W3_lo, g_W3_lo);

    const int SM_G = 2 * STG2 * (int)sizeof(__nv_bfloat16);   // 110592 (2 stages)
    const int SM_S = 6 * TSZE * (int)sizeof(__nv_bfloat16);   // 208896
    cudaFuncSetAttribute(hmma_gemm64, cudaFuncAttributeMaxDynamicSharedMemorySize, SM_G);
    cudaFuncSetAttribute(scores_pipe, cudaFuncAttributeMaxDynamicSharedMemorySize, SM_S);

    // stage 0: conversions + gather
    convert_params<<<(246400 + 255) / 256, 256>>>(ggnn_w, ggnn_b, gru_bhh,
                                                  gru_wih, gru_whh, W1_w, W2_w, W3_w);
    embed_gather<<<(NTOT * H / 4 + 255) / 256, 256>>>(x, emb);
    convert_emb<<<((long)NNODE * H / 4 + 255) / 256, 256>>>(emb);

    // stage 1: fused h -> [hin | hout | gg], Nc=640
    hmma_gemm64<<<dim3(5, NTOT / 64), 256, SM_G>>>(p_h_hi, p_h_lo, p_wcat_hi, p_wcat_lo,
                                                   p_bcat, p_pre, nullptr, nullptr, NTOT, 640, H);

    // stage 2: message passing
    msg_pass<<<BG, 128>>>(ei, ec, idi, odi);

    // stage 3: GRU input-path + gates
    hmma_gemm64<<<dim3(3, NTOT / 64), 256, SM_G>>>(p_m_hi, p_m_lo, p_wih_hi, p_wih_lo,
                                                   gru_bih, p_a, nullptr, nullptr, NTOT, 3 * H, 2 * H);
    gru_gates<<<(NTOT * 64 + 255) / 256, 256>>>();

    // stage 4: attention readout
    hmma_gemm64<<<dim3(1, BG / 64), 256, SM_G>>>(p_vn_hi, p_vn_lo, p_W1_hi, p_W1_lo,
                                                 W1_b, p_u, nullptr, nullptr, BG, H, H);
    hmma_gemm64<<<dim3(1, NTOT / 64), 256, SM_G>>>(p_hn_hi, p_hn_lo, p_W2_hi, p_W2_lo,
                                                   W2_b, p_t2, nullptr, nullptr, NTOT, H, H);
    attention<<<BG, 128>>>(q_w, q_b, ncnt);
    hmma_gemm64<<<dim3(1, BG / 64), 256, SM_G>>>(p_cat_hi, p_cat_lo, p_W3_hi, p_W3_lo,
                                                 W3_b, p_sh, p_sh_hi, p_sh_lo, BG, H, 2 * H);

    // stage 5: scores
    scores_pipe<<<dim3((NNODE + T_NT * 128 - 1) / (T_NT * 128), BG / 128), 512, SM_S>>>(out);
}

// round 17
// speedup vs baseline: 1.0377x; 1.0377x over previous
#include <cuda_runtime.h>
#include <cuda_bf16.h>
#include <math.h>
#include <cstdint>

#define H 128
#define BG 1024
#define NPER 32
#define NTOT (BG * NPER)      // 32768 nodes
#define ETOT (2 * NTOT)       // 65536 edges
#define NNODE 100000

#define SROW 136              // scores kernel smem row (bf16)
#define TSZE (128 * SROW)
#define T_NT 8                // n-tiles per block in scores kernel

#define SROW2 72              // mid-GEMM smem row (bf16), BK=64 + 8 pad
#define ATILE2 (64 * SROW2)   // 4608 elems
#define BTILE2 (128 * SROW2)  // 9216 elems
#define STG2 (2 * ATILE2 + 2 * BTILE2)   // 27648 elems per stage (55296 B)

// ---------------- device scratch ----------------
__device__ float g_h[NTOT * H];
__device__ __nv_bfloat16 g_h_hi[NTOT * H];
__device__ __nv_bfloat16 g_h_lo[NTOT * H];
__device__ float g_pre[NTOT * 640];       // [hin(128) | hout(128) | gg(384)] per node
__device__ __nv_bfloat16 g_m_hi[NTOT * 2 * H];
__device__ __nv_bfloat16 g_m_lo[NTOT * 2 * H];
__device__ float g_a[NTOT * 3 * H];
__device__ float g_hn[NTOT * H];
__device__ __nv_bfloat16 g_hn_hi[NTOT * H];
__device__ __nv_bfloat16 g_hn_lo[NTOT * H];
__device__ float g_t2[NTOT * H];
__device__ float g_vn[BG * H];
__device__ __nv_bfloat16 g_vn_hi[BG * H];
__device__ __nv_bfloat16 g_vn_lo[BG * H];
__device__ float g_u[BG * H];
__device__ __nv_bfloat16 g_cat_hi[BG * 2 * H];
__device__ __nv_bfloat16 g_cat_lo[BG * 2 * H];
__device__ float g_sh[BG * H];
__device__ __nv_bfloat16 g_sh_hi[BG * H];
__device__ __nv_bfloat16 g_sh_lo[BG * H];
__device__ __nv_bfloat16 g_wcat_hi[640 * H];   // [wT0;wT1;whh] as [out][in]
__device__ __nv_bfloat16 g_wcat_lo[640 * H];
__device__ float g_bcat[640];                  // [ggnn_b(256); gru_bhh(384)]
__device__ __nv_bfloat16 g_wih_hi[3 * H * 2 * H];
__device__ __nv_bfloat16 g_wih_lo[3 * H * 2 * H];
__device__ __nv_bfloat16 g_W1_hi[H * H];
__device__ __nv_bfloat16 g_W1_lo[H * H];
__device__ __nv_bfloat16 g_W2_hi[H * H];
__device__ __nv_bfloat16 g_W2_lo[H * H];
__device__ __nv_bfloat16 g_W3_hi[H * 2 * H];
__device__ __nv_bfloat16 g_W3_lo[H * 2 * H];
__device__ __nv_bfloat16 g_emb_hi[NNODE * H];
__device__ __nv_bfloat16 g_emb_lo[NNODE * H];

// ======================= helpers =======================
__device__ __forceinline__ uint32_t smem_u32(const void* p) {
    uint32_t a;
    asm("{ .reg .u64 t; cvta.to.shared.u64 t, %1; cvt.u32.u64 %0, t; }" : "=r"(a) : "l"(p));
    return a;
}
__device__ __forceinline__ void ldsm_x4(uint32_t* r, uint32_t addr) {
    asm volatile("ldmatrix.sync.aligned.m8n8.x4.shared.b16 {%0,%1,%2,%3}, [%4];"
        : "=r"(r[0]), "=r"(r[1]), "=r"(r[2]), "=r"(r[3]) : "r"(addr));
}
__device__ __forceinline__ void mma_bf16(float* c, const uint32_t* a, const uint32_t* b) {
    asm volatile(
        "mma.sync.aligned.m16n8k16.row.col.f32.bf16.bf16.f32 "
        "{%0,%1,%2,%3}, {%4,%5,%6,%7}, {%8,%9}, {%0,%1,%2,%3};"
        : "+f"(c[0]), "+f"(c[1]), "+f"(c[2]), "+f"(c[3])
        : "r"(a[0]), "r"(a[1]), "r"(a[2]), "r"(a[3]),
          "r"(b[0]), "r"(b[1]));
}
__device__ __forceinline__ void cp16(uint32_t dst, const void* src, bool p) {
    int sz = p ? 16 : 0;
    asm volatile("cp.async.cg.shared.global [%0], [%1], 16, %2;"
        :: "r"(dst), "l"(src), "r"(sz) : "memory");
}
__device__ __forceinline__ void split2(float x, __nv_bfloat16* hi, __nv_bfloat16* lo) {
    __nv_bfloat16 h = __float2bfloat16_rn(x);
    *hi = h;
    *lo = __float2bfloat16_rn(x - __bfloat162float(h));
}
__device__ __forceinline__ uint32_t pack2(float a, float b, float* rlo0, float* rlo1) {
    __nv_bfloat16 ha = __float2bfloat16_rn(a), hb = __float2bfloat16_rn(b);
    *rlo0 = a - __bfloat162float(ha);
    *rlo1 = b - __bfloat162float(hb);
    __nv_bfloat162 p = __halves2bfloat162(ha, hb);
    return *(uint32_t*)&p;
}
__device__ __forceinline__ uint32_t packlo(float l0, float l1) {
    __nv_bfloat162 p = __halves2bfloat162(__float2bfloat16_rn(l0), __float2bfloat16_rn(l1));
    return *(uint32_t*)&p;
}

// ============ mid split-bf16 HMMA GEMM: C[M,Nc] = A[M,K] @ B[Nc,K]^T + bias ============
// block tile 64x128, BK=64 double-buffered, 8 warps (2m x 4n), warp 32x32. 2 CTAs/SM.
// MMA issued in 3 product passes to break accumulator RAW chains.
__global__ __launch_bounds__(256, 2) void hmma_gemm64(
    const __nv_bfloat16* __restrict__ Ahi, const __nv_bfloat16* __restrict__ Alo,
    const __nv_bfloat16* __restrict__ Bhi, const __nv_bfloat16* __restrict__ Blo,
    const float* __restrict__ bias, float* __restrict__ C,
    __nv_bfloat16* __restrict__ Chi, __nv_bfloat16* __restrict__ Clo,
    int M, int Nc, int K)
{
    extern __shared__ __align__(16) __nv_bfloat16 smem[];
    const int tid = threadIdx.x;
    const int m0 = blockIdx.y * 64;
    const int n0 = blockIdx.x * 128;
    const int w = tid >> 5, lane = tid & 31;
    const int wm = (w >> 2) * 32, wn = (w & 3) * 32;
    const int Kv = K >> 3;
    const int nk = K >> 6;

    float acc[2][4][4];
#pragma unroll
    for (int i = 0; i < 2; i++)
#pragma unroll
        for (int j = 0; j < 4; j++)
#pragma unroll
            for (int v = 0; v < 4; v++) acc[i][j][v] = 0.f;

    const uint32_t sbase = smem_u32(smem);
    const int aRow = (lane & 7) + ((lane >> 3) & 1) * 8;
    const int aK   = (lane >> 4) * 8;
    const int bRow = (lane & 7) + (lane >> 4) * 8;
    const int bK   = ((lane >> 3) & 1) * 8;

    auto fill = [&](int c, int s) {
        const uint32_t st = sbase + s * STG2 * 2;
        const uint32_t aHi = st, aLo = st + ATILE2 * 2;
        const uint32_t bHi = st + 2 * ATILE2 * 2, bLo = bHi + BTILE2 * 2;
        const int kv0 = c * 8;
#pragma unroll
        for (int it = 0; it < 2; it++) {
            int idx = tid + it * 256;
            int row = idx >> 3, u = idx & 7;
            cp16(aHi + (row * SROW2 + u * 8) * 2, (const uint4*)Ahi + (size_t)(m0 + row) * Kv + kv0 + u, true);
            cp16(aLo + (row * SROW2 + u * 8) * 2, (const uint4*)Alo + (size_t)(m0 + row) * Kv + kv0 + u, true);
        }
#pragma unroll
        for (int it = 0; it < 4; it++) {
            int idx = tid + it * 256;
            int row = idx >> 3, u = idx & 7;
            int gr = n0 + row;
            bool p = gr < Nc;
            size_t off = p ? ((size_t)gr * Kv + kv0 + u) : 0;
            cp16(bHi + (row * SROW2 + u * 8) * 2, (const uint4*)Bhi + off, p);
            cp16(bLo + (row * SROW2 + u * 8) * 2, (const uint4*)Blo + off, p);
        }
        asm volatile("cp.async.commit_group;" ::: "memory");
    };

    fill(0, 0);
    if (nk > 1) fill(1, 1);

    for (int c = 0; c < nk; c++) {
        if (c + 1 < nk) asm volatile("cp.async.wait_group 1;" ::: "memory");
        else            asm volatile("cp.async.wait_group 0;" ::: "memory");
        __syncthreads();
        const int s = c & 1;
        const uint32_t st = sbase + s * STG2 * 2;
        const uint32_t aHiB = st, aLoB = st + ATILE2 * 2;
        const uint32_t bHiB = st + 2 * ATILE2 * 2, bLoB = bHiB + BTILE2 * 2;

#pragma unroll
        for (int ks = 0; ks < 4; ks++) {
            const int k0 = ks * 16;
            uint32_t ahi[2][4], alo[2][4], bhi[2][4], blo[2][4];
#pragma unroll
            for (int i = 0; i < 2; i++) {
                uint32_t off = (uint32_t)((wm + i * 16 + aRow) * SROW2 + k0 + aK) * 2;
                ldsm_x4(ahi[i], aHiB + off);
                ldsm_x4(alo[i], aLoB + off);
            }
#pragma unroll
            for (int q = 0; q < 2; q++) {
                uint32_t off = (uint32_t)((wn + q * 16 + bRow) * SROW2 + k0 + bK) * 2;
                ldsm_x4(bhi[q], bHiB + off);
                ldsm_x4(blo[q], bLoB + off);
            }
            // pass 0: hi*hi (8 independent accs between same-acc reuse)
#pragma unroll
            for (int i = 0; i < 2; i++)
#pragma unroll
                for (int j = 0; j < 4; j++)
                    mma_bf16(acc[i][j], ahi[i], &bhi[j >> 1][(j & 1) * 2]);
            // pass 1: lo*hi
#pragma unroll
            for (int i = 0; i < 2; i++)
#pragma unroll
                for (int j = 0; j < 4; j++)
                    mma_bf16(acc[i][j], alo[i], &bhi[j >> 1][(j & 1) * 2]);
            // pass 2: hi*lo
#pragma unroll
            for (int i = 0; i < 2; i++)
#pragma unroll
                for (int j = 0; j < 4; j++)
                    mma_bf16(acc[i][j], ahi[i], &blo[j >> 1][(j & 1) * 2]);
        }
        __syncthreads();
        if (c + 2 < nk) fill(c + 2, s);
    }

#pragma unroll
    for (int i = 0; i < 2; i++) {
        int row = m0 + wm + i * 16 + (lane >> 2);
#pragma unroll
        for (int j = 0; j < 4; j++) {
            int col = n0 + wn + j * 8 + (lane & 3) * 2;
            if (col < Nc) {
                float b0 = bias ? bias[col] : 0.f;
                float b1 = bias ? bias[col + 1] : 0.f;
                float v0 = acc[i][j][0] + b0, v1 = acc[i][j][1] + b1;
                float v2 = acc[i][j][2] + b0, v3 = acc[i][j][3] + b1;
                *(float2*)&C[(size_t)row * Nc + col] = make_float2(v0, v1);
                *(float2*)&C[(size_t)(row + 8) * Nc + col] = make_float2(v2, v3);
                if (Chi) {
                    float l0, l1;
                    uint32_t ph = pack2(v0, v1, &l0, &l1);
                    *(uint32_t*)&Chi[(size_t)row * Nc + col] = ph;
                    *(uint32_t*)&Clo[(size_t)row * Nc + col] = packlo(l0, l1);
                    uint32_t ph2 = pack2(v2, v3, &l0, &l1);
                    *(uint32_t*)&Chi[(size_t)(row + 8) * Nc + col] = ph2;
                    *(uint32_t*)&Clo[(size_t)(row + 8) * Nc + col] = packlo(l0, l1);
                }
            }
        }
    }
}

// ============ scores GEMM: C[1024,100000] = sh @ emb^T — 256 thr, warp tile 32x64 ============
// MMA in 3 product passes (16 independent accs between same-acc reuse).
__global__ __launch_bounds__(256) void scores_pipe(float* __restrict__ C) {
    extern __shared__ __align__(16) __nv_bfloat16 smem[];
    __nv_bfloat16* sAhi = smem;
    __nv_bfloat16* sAlo = smem + TSZE;
    __nv_bfloat16* sB   = smem + 2 * TSZE;   // stage s: hi at (2s)*TSZE, lo at (2s+1)*TSZE
    const int tid = threadIdx.x;
    const int m0 = blockIdx.y * 128;
    const int nb0 = blockIdx.x * (T_NT * 128);

    const uint4* bh = (const uint4*)g_emb_hi;
    const uint4* bl = (const uint4*)g_emb_lo;

    {
#pragma unroll
        for (int it = 0; it < 8; it++) {
            int idx = tid + it * 256;
            int row = idx >> 4, u = idx & 15;
            int gr = nb0 + row;
            bool p = gr < NNODE;
            size_t off = p ? ((size_t)gr * 16 + u) : 0;
            cp16(smem_u32(sB + row * SROW + u * 8), bh + off, p);
            cp16(smem_u32(sB + TSZE + row * SROW + u * 8), bl + off, p);
        }
        const uint4* ah = (const uint4*)g_sh_hi;
        const uint4* al = (const uint4*)g_sh_lo;
#pragma unroll
        for (int it = 0; it < 8; it++) {
            int idx = tid + it * 256;
            int row = idx >> 4, u = idx & 15;
            cp16(smem_u32(sAhi + row * SROW + u * 8), ah + (size_t)(m0 + row) * 16 + u, true);
            cp16(smem_u32(sAlo + row * SROW + u * 8), al + (size_t)(m0 + row) * 16 + u, true);
        }
        asm volatile("cp.async.commit_group;" ::: "memory");
    }
    {
#pragma unroll
        for (int it = 0; it < 8; it++) {
            int idx = tid + it * 256;
            int row = idx >> 4, u = idx & 15;
            int gr = nb0 + 128 + row;
            bool p = gr < NNODE;
            size_t off = p ? ((size_t)gr * 16 + u) : 0;
            cp16(smem_u32(sB + 2 * TSZE + row * SROW + u * 8), bh + off, p);
            cp16(smem_u32(sB + 3 * TSZE + row * SROW + u * 8), bl + off, p);
        }
        asm volatile("cp.async.commit_group;" ::: "memory");
    }

    const uint32_t aHiB = smem_u32(sAhi), aLoB = smem_u32(sAlo);
    const int w = tid >> 5, lane = tid & 31;
    const int wm = (w >> 1) * 32, wn = (w & 1) * 64;
    const int aRow = (lane & 7) + ((lane >> 3) & 1) * 8;
    const int aK   = (lane >> 4) * 8;
    const int bRow = (lane & 7) + (lane >> 4) * 8;
    const int bK   = ((lane >> 3) & 1) * 8;

#pragma unroll
    for (int t = 0; t < T_NT; t++) {
        if (t + 1 < T_NT) asm volatile("cp.async.wait_group 1;" ::: "memory");
        else              asm volatile("cp.async.wait_group 0;" ::: "memory");
        __syncthreads();
        const int s = t & 1;
        const uint32_t bHiB = smem_u32(sB + (2 * s) * TSZE);
        const uint32_t bLoB = smem_u32(sB + (2 * s + 1) * TSZE);

        float acc[2][8][4];
#pragma unroll
        for (int i = 0; i < 2; i++)
#pragma unroll
            for (int j = 0; j < 8; j++)
#pragma unroll
                for (int v = 0; v < 4; v++) acc[i][j][v] = 0.f;

#pragma unroll
        for (int ks = 0; ks < 8; ks++) {
            const int k0 = ks * 16;
            uint32_t ahi[2][4], alo[2][4], bhi[4][4], blo[4][4];
#pragma unroll
            for (int i = 0; i < 2; i++) {
                uint32_t off = (uint32_t)((wm + i * 16 + aRow) * SROW + k0 + aK) * 2;
                ldsm_x4(ahi[i], aHiB + off);
                ldsm_x4(alo[i], aLoB + off);
            }
#pragma unroll
            for (int q = 0; q < 4; q++) {
                uint32_t off = (uint32_t)((wn + q * 16 + bRow) * SROW + k0 + bK) * 2;
                ldsm_x4(bhi[q], bHiB + off);
                ldsm_x4(blo[q], bLoB + off);
            }
            // pass 0: hi*hi
#pragma unroll
            for (int i = 0; i < 2; i++)
#pragma unroll
                for (int j = 0; j < 8; j++)
                    mma_bf16(acc[i][j], ahi[i], &bhi[j >> 1][(j & 1) * 2]);
            // pass 1: lo*hi
#pragma unroll
            for (int i = 0; i < 2; i++)
#pragma unroll
                for (int j = 0; j < 8; j++)
                    mma_bf16(acc[i][j], alo[i], &bhi[j >> 1][(j & 1) * 2]);
            // pass 2: hi*lo
#pragma unroll
            for (int i = 0; i < 2; i++)
#pragma unroll
                for (int j = 0; j < 8; j++)
                    mma_bf16(acc[i][j], ahi[i], &blo[j >> 1][(j & 1) * 2]);
        }
        __syncthreads();

        if (t + 2 < T_NT) {
            int base = nb0 + (t + 2) * 128;
#pragma unroll
            for (int it = 0; it < 8; it++) {
                int idx = tid + it * 256;
                int row = idx >> 4, u = idx & 15;
                int gr = base + row;
                bool p = gr < NNODE;
                size_t off = p ? ((size_t)gr * 16 + u) : 0;
                cp16(smem_u32(sB + (2 * s) * TSZE + row * SROW + u * 8), bh + off, p);
                cp16(smem_u32(sB + (2 * s + 1) * TSZE + row * SROW + u * 8), bl + off, p);
            }
            asm volatile("cp.async.commit_group;" ::: "memory");
        }

        const int n0 = nb0 + t * 128;
#pragma unroll
        for (int i = 0; i < 2; i++) {
            int row = m0 + wm + i * 16 + (lane >> 2);
#pragma unroll
            for (int j = 0; j < 8; j++) {
                int col = n0 + wn + j * 8 + (lane & 3) * 2;
                if (col < NNODE) {
                    *(float2*)&C[(size_t)row * NNODE + col] =
                        make_float2(acc[i][j][0], acc[i][j][1]);
                    *(float2*)&C[(size_t)(row + 8) * NNODE + col] =
                        make_float2(acc[i][j][2], acc[i][j][3]);
                }
            }
        }
    }
}

// ---------------- fused prep: convert_emb + embed_gather + convert_params ----------------
#define N_EMB4 ((long)NNODE * H / 4)       // 3,200,000
#define N_GTH4 (NTOT * H / 4)              // 1,048,576
#define N_PRM  246400
#define N_PREP (N_EMB4 + N_GTH4 + N_PRM)

__global__ void prep_all(const int* __restrict__ x, const float* __restrict__ emb,
                         const float* __restrict__ gw, const float* __restrict__ ggb,
                         const float* __restrict__ bhh,
                         const float* __restrict__ wih, const float* __restrict__ whh,
                         const float* __restrict__ W1, const float* __restrict__ W2,
                         const float* __restrict__ W3) {
    long i = (long)blockIdx.x * blockDim.x + threadIdx.x;
    if (i < N_EMB4) {                       // convert_emb (float4 index)
        float4 v = ((const float4*)emb)[i];
        float l0, l1, l2, l3;
        uint32_t h01 = pack2(v.x, v.y, &l0, &l1);
        uint32_t h23 = pack2(v.z, v.w, &l2, &l3);
        ((uint2*)g_emb_hi)[i] = make_uint2(h01, h23);
        ((uint2*)g_emb_lo)[i] = make_uint2(packlo(l0, l1), packlo(l2, l3));
        return;
    }
    i -= N_EMB4;
    if (i < N_GTH4) {                       // embed_gather
        int node = (int)(i >> 5);
        int c4 = (int)(i & 31);
        int item = x[node] - 1;
        float4 v = ((const float4*)emb)[(size_t)item * 32 + c4];
        ((float4*)g_h)[i] = v;
        float l0, l1, l2, l3;
        uint32_t h01 = pack2(v.x, v.y, &l0, &l1);
        uint32_t h23 = pack2(v.z, v.w, &l2, &l3);
        ((uint2*)g_h_hi)[i] = make_uint2(h01, h23);
        ((uint2*)g_h_lo)[i] = make_uint2(packlo(l0, l1), packlo(l2, l3));
        return;
    }
    i -= N_GTH4;
    int k = (int)i;
    if (k < 32768) {                        // ggnn_w transpose -> wcat rows 0..255
        int l = k >> 14, r = (k >> 7) & 127, c = k & 127;
        int o = (l * H + c) * H + r;
        split2(gw[k], &g_wcat_hi[o], &g_wcat_lo[o]);
        return;
    }
    k -= 32768;
    if (k < 49152) { split2(whh[k], &g_wcat_hi[32768 + k], &g_wcat_lo[32768 + k]); return; }
    k -= 49152;
    if (k < 98304) { split2(wih[k], &g_wih_hi[k], &g_wih_lo[k]); return; }
    k -= 98304;
    if (k < 16384) { split2(W1[k], &g_W1_hi[k], &g_W1_lo[k]); return; }
    k -= 16384;
    if (k < 16384) { split2(W2[k], &g_W2_hi[k], &g_W2_lo[k]); return; }
    k -= 16384;
    if (k < 32768) { split2(W3[k], &g_W3_hi[k], &g_W3_lo[k]); return; }
    k -= 32768;
    if (k < 640) { g_bcat[k] = (k < 256) ? ggb[k] : bhh[k - 256]; return; }
}

// ---------------- stage kernels ----------------
__global__ __launch_bounds__(128) void msg_pass(
    const int* __restrict__ ei, const float* __restrict__ ec,
    const float* __restrict__ idi, const float* __restrict__ odi)
{
    __shared__ float hs[NPER][H];
    __shared__ float ms[NPER][H];
    __shared__ int es[64], ed[64];
    __shared__ float ws[64];
    const int g = blockIdx.x;
    const int f = threadIdx.x;
    const int nb = g * NPER, eb = g * 64;

    if (f < 64) {
        es[f] = ei[eb + f] - nb;
        ed[f] = ei[ETOT + eb + f] - nb;
        ws[f] = ec[eb + f] * idi[eb + f];
    }
    for (int i = 0; i < NPER; i++) {
        hs[i][f] = g_pre[(size_t)(nb + i) * 640 + f];          // hin
        ms[i][f] = 0.f;
    }
    __syncthreads();
    for (int e = 0; e < 64; e++)
        ms[ed[e]][f] += ws[e] * hs[es[e]][f];
    __syncthreads();
    for (int i = 0; i < NPER; i++) {
        size_t o = (size_t)(nb + i) * 2 * H + f;
        split2(ms[i][f], &g_m_hi[o], &g_m_lo[o]);
    }
    __syncthreads();

    if (f < 64) ws[f] = ec[eb + f] * odi[eb + f];
    for (int i = 0; i < NPER; i++) {
        hs[i][f] = g_pre[(size_t)(nb + i) * 640 + H + f];      // hout
        ms[i][f] = 0.f;
    }
    __syncthreads();
    for (int e = 0; e < 64; e++)
        ms[es[e]][f] += ws[e] * hs[ed[e]][f];
    __syncthreads();
    for (int i = 0; i < NPER; i++) {
        size_t o = (size_t)(nb + i) * 2 * H + H + f;
        split2(ms[i][f], &g_m_hi[o], &g_m_lo[o]);
    }
}

__global__ void gru_gates() {
    int idx = blockIdx.x * blockDim.x + threadIdx.x;   // pair index
    if (idx >= NTOT * 64) return;
    int i = idx >> 6, j = (idx & 63) * 2;
    size_t b3 = (size_t)i * 384;
    size_t bg = (size_t)i * 640 + 256;
    float2 a0 = *(float2*)&g_a[b3 + j];
    float2 g0 = *(float2*)&g_pre[bg + j];
    float2 a1 = *(float2*)&g_a[b3 + 128 + j];
    float2 g1 = *(float2*)&g_pre[bg + 128 + j];
    float2 a2 = *(float2*)&g_a[b3 + 256 + j];
    float2 g2 = *(float2*)&g_pre[bg + 256 + j];
    float2 h  = *(float2*)&g_h[(size_t)i * H + j];

    float r0 = 1.f / (1.f + __expf(-(a0.x + g0.x)));
    float r1 = 1.f / (1.f + __expf(-(a0.y + g0.y)));
    float z0 = 1.f / (1.f + __expf(-(a1.x + g1.x)));
    float z1 = 1.f / (1.f + __expf(-(a1.y + g1.y)));
    float n0 = tanhf(a2.x + r0 * g2.x);
    float n1 = tanhf(a2.y + r1 * g2.y);
    float o0 = (1.f - z0) * n0 + z0 * h.x;
    float o1 = (1.f - z1) * n1 + z1 * h.y;

    size_t o = (size_t)i * H + j;
    *(float2*)&g_hn[o] = make_float2(o0, o1);
    float l0, l1;
    uint32_t ph = pack2(o0, o1, &l0, &l1);
    *(uint32_t*)&g_hn_hi[o] = ph;
    *(uint32_t*)&g_hn_lo[o] = packlo(l0, l1);
    if ((i & 31) == 31) {
        size_t ov = (size_t)(i >> 5) * H + j;
        *(float2*)&g_vn[ov] = make_float2(o0, o1);
        *(uint32_t*)&g_vn_hi[ov] = ph;
        *(uint32_t*)&g_vn_lo[ov] = packlo(l0, l1);
    }
}

__global__ __launch_bounds__(128) void attention(
    const float* __restrict__ qw, const float* __restrict__ qb,
    const float* __restrict__ ncnt)
{
    __shared__ float coef[NPER];
    const int g = blockIdx.x;
    const int tid = threadIdx.x;
    const int w = tid >> 5, l = tid & 31;

    for (int ii = 0; ii < 8; ii++) {
        int i = w * 8 + ii;
        int node = g * NPER + i;
        float p = 0.f;
#pragma unroll
        for (int c = 0; c < 4; c++) {
            int fd = l + c * 32;
            float s = g_u[g * H + fd] + g_t2[(size_t)node * H + fd];
            p += qw[fd] / (1.f + __expf(-s));
        }
#pragma unroll
        for (int off = 16; off; off >>= 1)
            p += __shfl_xor_sync(0xffffffff, p, off);
        if (l == 0) coef[i] = (p + qb[0]) * ncnt[node];
    }
    __syncthreads();

    const int f = tid;
    float acc = 0.f;
    for (int i = 0; i < NPER; i++)
        acc += coef[i] * g_hn[(size_t)(g * NPER + i) * H + f];
    size_t o = (size_t)g * 2 * H;
    split2(acc, &g_cat_hi[o + H + f], &g_cat_lo[o + H + f]);
    split2(g_vn[g * H + f], &g_cat_hi[o + f], &g_cat_lo[o + f]);
}

// ---------------- launch ----------------
extern "C" void kernel_launch(void* const* d_in, const int* in_sizes, int n_in,
                              void* d_out, int out_size)
{
    const int*   x       = (const int*)d_in[0];
    const int*   ei      = (const int*)d_in[1];
    const float* ec      = (const float*)d_in[3];
    const float* idi     = (const float*)d_in[4];
    const float* odi     = (const float*)d_in[5];
    const float* ncnt    = (const float*)d_in[6];
    const float* emb     = (const float*)d_in[8];
    const float* ggnn_w  = (const float*)d_in[9];
    const float* ggnn_b  = (const float*)d_in[10];
    const float* gru_wih = (const float*)d_in[11];
    const float* gru_whh = (const float*)d_in[12];
    const float* gru_bih = (const float*)d_in[13];
    const float* gru_bhh = (const float*)d_in[14];
    const float* W1_w = (const float*)d_in[15];
    const float* W1_b = (const float*)d_in[16];
    const float* W2_w = (const float*)d_in[17];
    const float* W2_b = (const float*)d_in[18];
    const float* q_w  = (const float*)d_in[19];
    const float* q_b  = (const float*)d_in[20];
    const float* W3_w = (const float*)d_in[21];
    const float* W3_b = (const float*)d_in[22];
    float* out = (float*)d_out;

    float *p_pre, *p_a, *p_t2, *p_u, *p_sh, *p_bcat;
    __nv_bfloat16 *p_h_hi, *p_h_lo, *p_m_hi, *p_m_lo, *p_hn_hi, *p_hn_lo;
    __nv_bfloat16 *p_vn_hi, *p_vn_lo, *p_cat_hi, *p_cat_lo, *p_sh_hi, *p_sh_lo;
    __nv_bfloat16 *p_wcat_hi, *p_wcat_lo, *p_wih_hi, *p_wih_lo;
    __nv_bfloat16 *p_W1_hi, *p_W1_lo, *p_W2_hi, *p_W2_lo, *p_W3_hi, *p_W3_lo;
    cudaGetSymbolAddress((void**)&p_pre, g_pre);
    cudaGetSymbolAddress((void**)&p_a, g_a);
    cudaGetSymbolAddress((void**)&p_t2, g_t2);
    cudaGetSymbolAddress((void**)&p_u, g_u);
    cudaGetSymbolAddress((void**)&p_sh, g_sh);
    cudaGetSymbolAddress((void**)&p_bcat, g_bcat);
    cudaGetSymbolAddress((void**)&p_h_hi, g_h_hi);
    cudaGetSymbolAddress((void**)&p_h_lo, g_h_lo);
    cudaGetSymbolAddress((void**)&p_m_hi, g_m_hi);
    cudaGetSymbolAddress((void**)&p_m_lo, g_m_lo);
    cudaGetSymbolAddress((void**)&p_hn_hi, g_hn_hi);
    cudaGetSymbolAddress((void**)&p_hn_lo, g_hn_lo);
    cudaGetSymbolAddress((void**)&p_vn_hi, g_vn_hi);
    cudaGetSymbolAddress((void**)&p_vn_lo, g_vn_lo);
    cudaGetSymbolAddress((void**)&p_cat_hi, g_cat_hi);
    cudaGetSymbolAddress((void**)&p_cat_lo, g_cat_lo);
    cudaGetSymbolAddress((void**)&p_sh_hi, g_sh_hi);
    cudaGetSymbolAddress((void**)&p_sh_lo, g_sh_lo);
    cudaGetSymbolAddress((void**)&p_wcat_hi, g_wcat_hi);
    cudaGetSymbolAddress((void**)&p_wcat_lo, g_wcat_lo);
    cudaGetSymbolAddress((void**)&p_wih_hi, g_wih_hi);
    cudaGetSymbolAddress((void**)&p_wih_lo, g_wih_lo);
    cudaGetSymbolAddress((void**)&p_W1_hi, g_W1_hi);
    cudaGetSymbolAddress((void**)&p_W1_lo, g_W1_lo);
    cudaGetSymbolAddress((void**)&p_W2_hi, g_W2_hi);
    cudaGetSymbolAddress((void**)&p_W2_lo, g_W2_lo);
    cudaGetSymbolAddress((void**)&p_W3_hi, g_W3_hi);
    cudaGetSymbolAddress((void**)&p_W3_lo, g_W3_lo);

    const int SM_G = 2 * STG2 * (int)sizeof(__nv_bfloat16);   // 110592 (2 stages)
    const int SM_S = 6 * TSZE * (int)sizeof(__nv_bfloat16);   // 208896
    cudaFuncSetAttribute(hmma_gemm64, cudaFuncAttributeMaxDynamicSharedMemorySize, SM_G);
    cudaFuncSetAttribute(scores_pipe, cudaFuncAttributeMaxDynamicSharedMemorySize, SM_S);

    // stage 0: fused conversions + gather
    prep_all<<<(int)((N_PREP + 255) / 256), 256>>>(x, emb, ggnn_w, ggnn_b, gru_bhh,
                                                   gru_wih, gru_whh, W1_w, W2_w, W3_w);

    // stage 1: fused h -> [hin | hout | gg], Nc=640
    hmma_gemm64<<<dim3(5, NTOT / 64), 256, SM_G>>>(p_h_hi, p_h_lo, p_wcat_hi, p_wcat_lo,
                                                   p_bcat, p_pre, nullptr, nullptr, NTOT, 640, H);

    // stage 2: message passing
    msg_pass<<<BG, 128>>>(ei, ec, idi, odi);

    // stage 3: GRU input-path + gates
    hmma_gemm64<<<dim3(3, NTOT / 64), 256, SM_G>>>(p_m_hi, p_m_lo, p_wih_hi, p_wih_lo,
                                                   gru_bih, p_a, nullptr, nullptr, NTOT, 3 * H, 2 * H);
    gru_gates<<<(NTOT * 64 + 255) / 256, 256>>>();

    // stage 4: attention readout
    hmma_gemm64<<<dim3(1, BG / 64), 256, SM_G>>>(p_vn_hi, p_vn_lo, p_W1_hi, p_W1_lo,
                                                 W1_b, p_u, nullptr, nullptr, BG, H, H);
    hmma_gemm64<<<dim3(1, NTOT / 64), 256, SM_G>>>(p_hn_hi, p_hn_lo, p_W2_hi, p_W2_lo,
                                                   W2_b, p_t2, nullptr, nullptr, NTOT, H, H);
    attention<<<BG, 128>>>(q_w, q_b, ncnt);
    hmma_gemm64<<<dim3(1, BG / 64), 256, SM_G>>>(p_cat_hi, p_cat_lo, p_W3_hi, p_W3_lo,
                                                 W3_b, p_sh, p_sh_hi, p_sh_lo, BG, H, 2 * H);

    // stage 5: scores
    scores_pipe<<<dim3((NNODE + T_NT * 128 - 1) / (T_NT * 128), BG / 128), 256, SM_S>>>(out);
}